// round 15
// baseline (speedup 1.0000x reference)
#include <cuda_runtime.h>
#include <cuda_fp16.h>
#include <math.h>

#define B_ROWS 8192
#define N_IN   12288
#define H0     256
#define H1     32
#define H2     32
#define CAP     192
#define NWARPS  8
#define N_TILES 3072            // 384 x 8 transpose tiles (32x32)
#define N_UNITS (2 * B_ROWS)    // (row, color)

// Transposed fp16 feature weights: wTh[j][h]; 6.3 MB, L2-resident
__device__ __half g_wTh[N_IN * H0];
// Per-(row,color) clipped FT halves: 16.8 MB staging (L2)
__device__ float g_half[(size_t)N_UNITS * H0];
// Row completion + dispatch/transpose counters
__device__ unsigned g_done[B_ROWS];
__device__ int g_rowCtr, g_tpCtr, g_tpDone;

__global__ void init_state() {
    const int i = blockIdx.x * blockDim.x + threadIdx.x;
    if (i < B_ROWS) g_done[i] = 0u;
    if (i == 0) { g_rowCtr = 0; g_tpCtr = 0; g_tpDone = 0; }
}

extern __shared__ __half2 s_l1h2[];   // [p*32 + kk]: (w[kk][2p], w[kk][2p+1]); 32 KB

__device__ __forceinline__ float clip01(float x) {
    return fminf(fmaxf(x, 0.f), 1.f);
}

// ---------------------------------------------------------------------------
// Fused kernel: transpose prologue (dynamic tiles) + warp-autonomous
// (row,color) units with half staging. 4 CTAs/SM (55.7 KB smem, <=64 regs).
// ---------------------------------------------------------------------------
__global__ void __launch_bounds__(256, 4)
nnue_fused(const float4* __restrict__ wfeat,
           const float4* __restrict__ bfeat,
           const unsigned int* __restrict__ side,
           const float* __restrict__ ft_w,
           const float* __restrict__ ft_b,
           const float* __restrict__ l1_w,
           const float* __restrict__ l1_b,
           const float* __restrict__ l2_w,
           const float* __restrict__ l2_b,
           const float* __restrict__ l3_w,
           const float* __restrict__ l3_b,
           float* __restrict__ out)
{
    __shared__ float s_l2wT[H1 * 33];
    __shared__ float s_o0[NWARPS][2 * H0];            // also transpose staging
    __shared__ unsigned short s_idx[NWARPS][CAP];
    __shared__ int s_t;

    const int tid  = threadIdx.x;
    const int warp = tid >> 5;
    const int lane = tid & 31;
    const unsigned lt = (1u << lane) - 1u;

    // ---- Prologue A: weight caches (stride-32 l1h2: lane-consecutive reads)
    for (int idx = tid; idx < H0 * H1; idx += 256) {
        const int p = idx >> 5, kk = idx & 31;
        s_l1h2[p * 32 + kk] =
            __floats2half2_rn(l1_w[kk * 2 * H0 + 2 * p], l1_w[kk * 2 * H0 + 2 * p + 1]);
    }
    for (int e = tid; e < H2 * H1; e += 256)
        s_l2wT[(e & 31) * 33 + (e >> 5)] = l2_w[e];

    float bias[8];
    #pragma unroll
    for (int q = 0; q < 4; q++) {
        bias[2 * q]     = ft_b[2 * lane + 64 * q];
        bias[2 * q + 1] = ft_b[2 * lane + 64 * q + 1];
    }
    const float l1b  = l1_b[lane];
    const float l2b  = l2_b[lane];
    const float l3w  = l3_w[lane];
    const float l3b0 = l3_b[0];
    const half2* __restrict__ wt2 = reinterpret_cast<const half2*>(g_wTh);

    // ---- Prologue B: cooperative transpose, dynamic 32x32 tiles.
    // 384 is NOT a power of two: true div/mod required (R13 lesson).
    {
        float (*s_tile)[33] = reinterpret_cast<float(*)[33]>(&s_o0[0][0]);
        const int tx = tid & 31, ty = tid >> 5;   // (32, 8)
        for (;;) {
            if (tid == 0) s_t = atomicAdd(&g_tpCtr, 1);
            __syncthreads();
            const int t = s_t;
            if (t >= N_TILES) break;
            const int jBase = (t % 384) * 32;
            const int hB    = (t / 384) * 32;
            #pragma unroll
            for (int r = ty; r < 32; r += 8)
                s_tile[r][tx] = ft_w[(size_t)(hB + r) * N_IN + (jBase + tx)];
            __syncthreads();
            #pragma unroll
            for (int r = ty; r < 32; r += 8)
                g_wTh[(size_t)(jBase + r) * H0 + (hB + tx)] =
                    __float2half_rn(s_tile[tx][r]);
            __threadfence();
            __syncthreads();
            if (tid == 0) atomicAdd(&g_tpDone, 1);
        }
        __syncthreads();
    }

    unsigned short* list = s_idx[warp];
    float* o0 = s_o0[warp];
    bool wt_ready = false;

    // Stream one color row (48 KB, 96 chunks, batches of 6), ballot-compact.
    auto scan = [&](const float4* __restrict__ rp) -> int {
        int n = 0;
        for (int ib = 0; ib < N_IN / 128; ib += 6) {   // 16 iterations
            float4 v[6];
            #pragma unroll
            for (int u = 0; u < 6; u++) v[u] = __ldcs(&rp[(ib + u) * 32 + lane]);
            #pragma unroll
            for (int u = 0; u < 6; u++) {
                const bool nz = (v[u].x != 0.f) | (v[u].y != 0.f) |
                                (v[u].z != 0.f) | (v[u].w != 0.f);
                if (__ballot_sync(0xffffffffu, nz) == 0u) continue;  // ~73% skip
                const int j0 = (ib + u) * 128 + 4 * lane;
                unsigned b;
                b = __ballot_sync(0xffffffffu, v[u].x != 0.f);
                if (v[u].x != 0.f) { int p = n + __popc(b & lt); if (p < CAP) list[p] = (unsigned short)j0; }
                n += __popc(b);
                b = __ballot_sync(0xffffffffu, v[u].y != 0.f);
                if (v[u].y != 0.f) { int p = n + __popc(b & lt); if (p < CAP) list[p] = (unsigned short)(j0 + 1); }
                n += __popc(b);
                b = __ballot_sync(0xffffffffu, v[u].z != 0.f);
                if (v[u].z != 0.f) { int p = n + __popc(b & lt); if (p < CAP) list[p] = (unsigned short)(j0 + 2); }
                n += __popc(b);
                b = __ballot_sync(0xffffffffu, v[u].w != 0.f);
                if (v[u].w != 0.f) { int p = n + __popc(b & lt); if (p < CAP) list[p] = (unsigned short)(j0 + 3); }
                n += __popc(b);
            }
        }
        return min(n, CAP);
    };

    // Gather: 4 indices x 4 half2 loads in flight (16 L2 loads / warp-iter).
    auto gather = [&](int n, float* acc) {
        int k = 0;
        for (; k + 3 < n; k += 4) {
            const int b0 = (int)list[k]     * (H0 / 2) + lane;
            const int b1 = (int)list[k + 1] * (H0 / 2) + lane;
            const int b2 = (int)list[k + 2] * (H0 / 2) + lane;
            const int b3 = (int)list[k + 3] * (H0 / 2) + lane;
            #pragma unroll
            for (int q = 0; q < 4; q++) {
                float2 f0 = __half22float2(wt2[b0 + 32 * q]);
                float2 f1 = __half22float2(wt2[b1 + 32 * q]);
                float2 f2 = __half22float2(wt2[b2 + 32 * q]);
                float2 f3 = __half22float2(wt2[b3 + 32 * q]);
                acc[2 * q]     += (f0.x + f1.x) + (f2.x + f3.x);
                acc[2 * q + 1] += (f0.y + f1.y) + (f2.y + f3.y);
            }
        }
        for (; k < n; k++) {
            const int b0 = (int)list[k] * (H0 / 2) + lane;
            #pragma unroll
            for (int q = 0; q < 4; q++) {
                float2 f0 = __half22float2(wt2[b0 + 32 * q]);
                acc[2 * q]     += f0.x;
                acc[2 * q + 1] += f0.y;
            }
        }
    };

    for (;;) {
        int u;
        if (lane == 0) u = atomicAdd(&g_rowCtr, 1);
        u = __shfl_sync(0xffffffffu, u, 0);
        if (u >= N_UNITS) break;
        const int row = u >> 1;
        const int col = u & 1;           // 0 = white, 1 = black

        // ---- Phase A: stream this color's features (DRAM), build list
        const int n = scan((col ? bfeat : wfeat) + (size_t)row * (N_IN / 4));
        __syncwarp();

        // One-time wait for fused transpose before first gather
        if (!wt_ready) {
            if (lane == 0)
                while (*(volatile int*)&g_tpDone < N_TILES) __nanosleep(64);
            __syncwarp();
            __threadfence();
            wt_ready = true;
        }

        // ---- Phase B: sparse FT gather (L2) + bias + clip
        float acc[8];
        #pragma unroll
        for (int i = 0; i < 8; i++) acc[i] = bias[i];
        gather(n, acc);
        #pragma unroll
        for (int i = 0; i < 8; i++) acc[i] = clip01(acc[i]);

        // ---- Phase C: publish this half; second arrival finishes the row
        float* hb = &g_half[(size_t)u * H0];
        #pragma unroll
        for (int q = 0; q < 4; q++)
            __stcs(reinterpret_cast<float2*>(hb + 64 * q + 2 * lane),
                   make_float2(acc[2 * q], acc[2 * q + 1]));
        __threadfence();
        unsigned old;
        if (lane == 0) old = atomicAdd(&g_done[row], 1u);
        old = __shfl_sync(0xffffffffu, old, 0);
        if (old == 0u) continue;        // first half done
        __threadfence();                // acquire: other half's stores visible

        // ---- Phase D0: assemble concat (own half = regs, other = L2)
        const bool sd = (side[row] != 0u);   // int32 (1) or fp32 (0x3F800000)
        const int baseOwn   = ((col == 0) == sd) ? 0 : H0;
        const int baseOther = H0 - baseOwn;
        const float* ho = &g_half[(size_t)(row * 2 + (1 - col)) * H0];
        #pragma unroll
        for (int q = 0; q < 4; q++) {
            const int h = 64 * q + 2 * lane;
            o0[baseOwn + h]     = acc[2 * q];
            o0[baseOwn + h + 1] = acc[2 * q + 1];
            const float2 p2 = __ldcg(reinterpret_cast<const float2*>(ho + h));
            o0[baseOther + h]     = p2.x;
            o0[baseOther + h + 1] = p2.y;
        }
        __syncwarp();

        // ---- Phase D: l1 (lane = output unit; fp16 weights, fp32 accum)
        float s = l1b;
        const float4* o04 = reinterpret_cast<const float4*>(o0);
        #pragma unroll 8
        for (int pp = 0; pp < (2 * H0) / 4; pp++) {
            const float4 ov = o04[pp];
            const float2 w0 = __half22float2(s_l1h2[(2 * pp)     * 32 + lane]);
            const float2 w1 = __half22float2(s_l1h2[(2 * pp + 1) * 32 + lane]);
            s += ov.x * w0.x + ov.y * w0.y + ov.z * w1.x + ov.w * w1.y;
        }
        const float o1 = clip01(s);

        // ---- Phase E: l2 via shfl broadcast, then l3 + sigmoid
        float s2 = l2b;
        #pragma unroll
        for (int i = 0; i < H1; i++)
            s2 += __shfl_sync(0xffffffffu, o1, i) * s_l2wT[i * 33 + lane];
        const float o2 = clip01(s2);

        float p = o2 * l3w;
        #pragma unroll
        for (int o = 16; o; o >>= 1) p += __shfl_xor_sync(0xffffffffu, p, o);
        if (lane == 0)
            out[row] = 1.f / (1.f + expf(-1.5f * (p + l3b0)));   // 300/200

        __syncwarp();   // o0/list reuse safety before next unit
    }
}

// ---------------------------------------------------------------------------
extern "C" void kernel_launch(void* const* d_in, const int* in_sizes, int n_in,
                              void* d_out, int out_size) {
    const float*        wfeat = (const float*)d_in[0];
    const float*        bfeat = (const float*)d_in[1];
    const unsigned int* side  = (const unsigned int*)d_in[2];
    const float*        ft_w  = (const float*)d_in[3];
    const float*        ft_b  = (const float*)d_in[4];
    const float*        l1_w  = (const float*)d_in[5];
    const float*        l1_b  = (const float*)d_in[6];
    const float*        l2_w  = (const float*)d_in[7];
    const float*        l2_b  = (const float*)d_in[8];
    const float*        l3_w  = (const float*)d_in[9];
    const float*        l3_b  = (const float*)d_in[10];
    float* out = (float*)d_out;

    // K1: reset counters (~1us)
    init_state<<<(B_ROWS + 255) / 256, 256>>>();

    // K2: fused kernel; 32KB dynamic smem; 4 CTAs/SM x 152 SMs = 608
    const int dyn_smem = H0 * 32 * (int)sizeof(__half2);   // 32768
    cudaFuncSetAttribute(nnue_fused, cudaFuncAttributeMaxDynamicSharedMemorySize, dyn_smem);
    nnue_fused<<<608, 256, dyn_smem>>>(
        (const float4*)wfeat, (const float4*)bfeat, side, ft_w,
        ft_b, l1_w, l1_b, l2_w, l2_b, l3_w, l3_b, out);
}

// round 16
// speedup vs baseline: 1.1612x; 1.1612x over previous
#include <cuda_runtime.h>
#include <cuda_fp16.h>
#include <math.h>

#define B_ROWS 8192
#define N_IN   12288
#define H0     256
#define H1     32
#define H2     32
#define CAP     192
#define NWARPS  8
#define N_TILES 3072            // 384 x 8 transpose tiles (32x32)
#define N_UNITS (2 * B_ROWS)    // (row, color)

// Transposed fp16 feature weights: wTh[j][h]; 6.3 MB, L2-resident
__device__ __half g_wTh[N_IN * H0];
// Per-(row,color) clipped FT halves: 16.8 MB staging (L2)
__device__ float g_half[(size_t)N_UNITS * H0];
// Row completion + dispatch/transpose counters
__device__ unsigned g_done[B_ROWS];
__device__ int g_rowCtr, g_tpCtr, g_tpDone;

__global__ void init_state() {
    const int i = blockIdx.x * blockDim.x + threadIdx.x;
    if (i < B_ROWS) g_done[i] = 0u;
    if (i == 0) { g_rowCtr = 0; g_tpCtr = 0; g_tpDone = 0; }
}

extern __shared__ __half2 s_l1h2[];   // [p*33 + kk]: (w[kk][2p], w[kk][2p+1]); 33.8 KB

__device__ __forceinline__ float clip01(float x) {
    return fminf(fmaxf(x, 0.f), 1.f);
}

// ---------------------------------------------------------------------------
// Fused kernel: transpose prologue (dynamic tiles) + R12's proven hot loop
// (half-row units, batch-8 scan, x4 gather). 3 CTAs/SM, no reg cap pressure.
// ---------------------------------------------------------------------------
__global__ void __launch_bounds__(256, 3)
nnue_fused(const float4* __restrict__ wfeat,
           const float4* __restrict__ bfeat,
           const unsigned int* __restrict__ side,
           const float* __restrict__ ft_w,
           const float* __restrict__ ft_b,
           const float* __restrict__ l1_w,
           const float* __restrict__ l1_b,
           const float* __restrict__ l2_w,
           const float* __restrict__ l2_b,
           const float* __restrict__ l3_w,
           const float* __restrict__ l3_b,
           float* __restrict__ out)
{
    __shared__ float s_l2wT[H1 * 33];
    __shared__ float s_o0[NWARPS][2 * H0];            // also transpose staging
    __shared__ unsigned short s_idx[NWARPS][CAP];
    __shared__ int s_t;

    const int tid  = threadIdx.x;
    const int warp = tid >> 5;
    const int lane = tid & 31;
    const unsigned lt = (1u << lane) - 1u;

    // ---- Prologue A: weight caches (stride-33, conflict-free)
    for (int idx = tid; idx < H0 * H1; idx += 256) {
        const int p = idx >> 5, kk = idx & 31;
        s_l1h2[p * 33 + kk] =
            __floats2half2_rn(l1_w[kk * 2 * H0 + 2 * p], l1_w[kk * 2 * H0 + 2 * p + 1]);
    }
    for (int e = tid; e < H2 * H1; e += 256)
        s_l2wT[(e & 31) * 33 + (e >> 5)] = l2_w[e];

    float bias[8];
    #pragma unroll
    for (int q = 0; q < 4; q++) {
        bias[2 * q]     = ft_b[2 * lane + 64 * q];
        bias[2 * q + 1] = ft_b[2 * lane + 64 * q + 1];
    }
    const float l1b  = l1_b[lane];
    const float l2b  = l2_b[lane];
    const float l3w  = l3_w[lane];
    const float l3b0 = l3_b[0];
    const half2* __restrict__ wt2 = reinterpret_cast<const half2*>(g_wTh);

    // ---- Prologue B: cooperative transpose, dynamic 32x32 tiles.
    // 384 is NOT a power of two: true div/mod required (R13 lesson).
    {
        float (*s_tile)[33] = reinterpret_cast<float(*)[33]>(&s_o0[0][0]);
        const int tx = tid & 31, ty = tid >> 5;   // (32, 8)
        for (;;) {
            if (tid == 0) s_t = atomicAdd(&g_tpCtr, 1);
            __syncthreads();
            const int t = s_t;
            if (t >= N_TILES) break;
            const int jBase = (t % 384) * 32;
            const int hB    = (t / 384) * 32;
            #pragma unroll
            for (int r = ty; r < 32; r += 8)
                s_tile[r][tx] = ft_w[(size_t)(hB + r) * N_IN + (jBase + tx)];
            __syncthreads();
            #pragma unroll
            for (int r = ty; r < 32; r += 8)
                g_wTh[(size_t)(jBase + r) * H0 + (hB + tx)] =
                    __float2half_rn(s_tile[tx][r]);
            __threadfence();
            __syncthreads();
            if (tid == 0) atomicAdd(&g_tpDone, 1);
        }
        __syncthreads();
    }

    unsigned short* list = s_idx[warp];
    float* o0 = s_o0[warp];
    bool wt_ready = false;

    // Stream one color row (48 KB, 96 chunks, batches of 8), ballot-compact.
    auto scan = [&](const float4* __restrict__ rp) -> int {
        int n = 0;
        for (int ib = 0; ib < N_IN / 128; ib += 8) {   // 12 iterations
            float4 v[8];
            #pragma unroll
            for (int u = 0; u < 8; u++) v[u] = __ldcs(&rp[(ib + u) * 32 + lane]);
            #pragma unroll
            for (int u = 0; u < 8; u++) {
                const bool nz = (v[u].x != 0.f) | (v[u].y != 0.f) |
                                (v[u].z != 0.f) | (v[u].w != 0.f);
                if (__ballot_sync(0xffffffffu, nz) == 0u) continue;  // ~73% skip
                const int j0 = (ib + u) * 128 + 4 * lane;
                unsigned b;
                b = __ballot_sync(0xffffffffu, v[u].x != 0.f);
                if (v[u].x != 0.f) { int p = n + __popc(b & lt); if (p < CAP) list[p] = (unsigned short)j0; }
                n += __popc(b);
                b = __ballot_sync(0xffffffffu, v[u].y != 0.f);
                if (v[u].y != 0.f) { int p = n + __popc(b & lt); if (p < CAP) list[p] = (unsigned short)(j0 + 1); }
                n += __popc(b);
                b = __ballot_sync(0xffffffffu, v[u].z != 0.f);
                if (v[u].z != 0.f) { int p = n + __popc(b & lt); if (p < CAP) list[p] = (unsigned short)(j0 + 2); }
                n += __popc(b);
                b = __ballot_sync(0xffffffffu, v[u].w != 0.f);
                if (v[u].w != 0.f) { int p = n + __popc(b & lt); if (p < CAP) list[p] = (unsigned short)(j0 + 3); }
                n += __popc(b);
            }
        }
        return min(n, CAP);
    };

    // Gather: 4 indices x 4 half2 loads in flight (16 L2 loads / warp-iter).
    auto gather = [&](int n, float* acc) {
        int k = 0;
        for (; k + 3 < n; k += 4) {
            const int b0 = (int)list[k]     * (H0 / 2) + lane;
            const int b1 = (int)list[k + 1] * (H0 / 2) + lane;
            const int b2 = (int)list[k + 2] * (H0 / 2) + lane;
            const int b3 = (int)list[k + 3] * (H0 / 2) + lane;
            #pragma unroll
            for (int q = 0; q < 4; q++) {
                float2 f0 = __half22float2(wt2[b0 + 32 * q]);
                float2 f1 = __half22float2(wt2[b1 + 32 * q]);
                float2 f2 = __half22float2(wt2[b2 + 32 * q]);
                float2 f3 = __half22float2(wt2[b3 + 32 * q]);
                acc[2 * q]     += (f0.x + f1.x) + (f2.x + f3.x);
                acc[2 * q + 1] += (f0.y + f1.y) + (f2.y + f3.y);
            }
        }
        for (; k < n; k++) {
            const int b0 = (int)list[k] * (H0 / 2) + lane;
            #pragma unroll
            for (int q = 0; q < 4; q++) {
                float2 f0 = __half22float2(wt2[b0 + 32 * q]);
                acc[2 * q]     += f0.x;
                acc[2 * q + 1] += f0.y;
            }
        }
    };

    for (;;) {
        int u;
        if (lane == 0) u = atomicAdd(&g_rowCtr, 1);
        u = __shfl_sync(0xffffffffu, u, 0);
        if (u >= N_UNITS) break;
        const int row = u >> 1;
        const int col = u & 1;           // 0 = white, 1 = black

        // ---- Phase A: stream this color's features (DRAM), build list
        const int n = scan((col ? bfeat : wfeat) + (size_t)row * (N_IN / 4));
        __syncwarp();

        // One-time wait for fused transpose before first gather
        if (!wt_ready) {
            if (lane == 0)
                while (*(volatile int*)&g_tpDone < N_TILES) __nanosleep(64);
            __syncwarp();
            __threadfence();
            wt_ready = true;
        }

        // ---- Phase B: sparse FT gather (L2) + bias + clip
        float acc[8];
        #pragma unroll
        for (int i = 0; i < 8; i++) acc[i] = bias[i];
        gather(n, acc);
        #pragma unroll
        for (int i = 0; i < 8; i++) acc[i] = clip01(acc[i]);

        // ---- Phase C: publish this half; second arrival finishes the row
        float* hb = &g_half[(size_t)u * H0];
        #pragma unroll
        for (int q = 0; q < 4; q++)
            __stcs(reinterpret_cast<float2*>(hb + 64 * q + 2 * lane),
                   make_float2(acc[2 * q], acc[2 * q + 1]));
        __threadfence();
        unsigned old;
        if (lane == 0) old = atomicAdd(&g_done[row], 1u);
        old = __shfl_sync(0xffffffffu, old, 0);
        if (old == 0u) continue;        // first half done
        __threadfence();                // acquire: other half's stores visible

        // ---- Phase D0: assemble concat (own half = regs, other = L2)
        const bool sd = (side[row] != 0u);   // int32 (1) or fp32 (0x3F800000)
        const int baseOwn   = ((col == 0) == sd) ? 0 : H0;
        const int baseOther = H0 - baseOwn;
        const float* ho = &g_half[(size_t)(row * 2 + (1 - col)) * H0];
        #pragma unroll
        for (int q = 0; q < 4; q++) {
            const int h = 64 * q + 2 * lane;
            o0[baseOwn + h]     = acc[2 * q];
            o0[baseOwn + h + 1] = acc[2 * q + 1];
            const float2 p2 = __ldcg(reinterpret_cast<const float2*>(ho + h));
            o0[baseOther + h]     = p2.x;
            o0[baseOther + h + 1] = p2.y;
        }
        __syncwarp();

        // ---- Phase D: l1 (lane = output unit; fp16 weights, fp32 accum)
        float s = l1b;
        const float4* o04 = reinterpret_cast<const float4*>(o0);
        #pragma unroll 8
        for (int pp = 0; pp < (2 * H0) / 4; pp++) {
            const float4 ov = o04[pp];
            const float2 w0 = __half22float2(s_l1h2[(2 * pp)     * 33 + lane]);
            const float2 w1 = __half22float2(s_l1h2[(2 * pp + 1) * 33 + lane]);
            s += ov.x * w0.x + ov.y * w0.y + ov.z * w1.x + ov.w * w1.y;
        }
        const float o1 = clip01(s);

        // ---- Phase E: l2 via shfl broadcast, then l3 + sigmoid
        float s2 = l2b;
        #pragma unroll
        for (int i = 0; i < H1; i++)
            s2 += __shfl_sync(0xffffffffu, o1, i) * s_l2wT[i * 33 + lane];
        const float o2 = clip01(s2);

        float p = o2 * l3w;
        #pragma unroll
        for (int o = 16; o; o >>= 1) p += __shfl_xor_sync(0xffffffffu, p, o);
        if (lane == 0)
            out[row] = 1.f / (1.f + expf(-1.5f * (p + l3b0)));   // 300/200

        __syncwarp();   // o0/list reuse safety before next unit
    }
}

// ---------------------------------------------------------------------------
extern "C" void kernel_launch(void* const* d_in, const int* in_sizes, int n_in,
                              void* d_out, int out_size) {
    const float*        wfeat = (const float*)d_in[0];
    const float*        bfeat = (const float*)d_in[1];
    const unsigned int* side  = (const unsigned int*)d_in[2];
    const float*        ft_w  = (const float*)d_in[3];
    const float*        ft_b  = (const float*)d_in[4];
    const float*        l1_w  = (const float*)d_in[5];
    const float*        l1_b  = (const float*)d_in[6];
    const float*        l2_w  = (const float*)d_in[7];
    const float*        l2_b  = (const float*)d_in[8];
    const float*        l3_w  = (const float*)d_in[9];
    const float*        l3_b  = (const float*)d_in[10];
    float* out = (float*)d_out;

    // K1: reset counters (~1us)
    init_state<<<(B_ROWS + 255) / 256, 256>>>();

    // K2: fused kernel; 33.8KB dynamic smem; 3 CTAs/SM x 152 SMs = 456
    const int dyn_smem = H0 * 33 * (int)sizeof(__half2);   // 33792
    cudaFuncSetAttribute(nnue_fused, cudaFuncAttributeMaxDynamicSharedMemorySize, dyn_smem);
    nnue_fused<<<456, 256, dyn_smem>>>(
        (const float4*)wfeat, (const float4*)bfeat, side, ft_w,
        ft_b, l1_w, l1_b, l2_w, l2_b, l3_w, l3_b, out);
}